// round 15
// baseline (speedup 1.0000x reference)
#include <cuda_runtime.h>
#include <cuda_bf16.h>
#include <math.h>

#define B 4
#define T 1024
#define D 512
#define U 32
#define WIDTH 64
#define EPS 1e-7f
#define TT 8
#define JW 71
#define JWP 72

#define LOG2E 1.4426950408889634f
#define C2    2.8853900817779268f   // 2*log2(e)

// Scratch: q' = (x@Wt + bh)*C2, k' = (x@Wx)*C2, [B,T,U]
__device__ __align__(16) float g_q[B * T * U];
__device__ __align__(16) float g_k[B * T * U];

typedef unsigned long long ull;

__device__ __forceinline__ void fma2(ull& acc, ull a, ull b) {
    asm("fma.rn.f32x2 %0, %1, %2, %0;" : "+l"(acc) : "l"(a), "l"(b));
}
__device__ __forceinline__ ull add2(ull a, ull b) {
    ull r; asm("add.rn.f32x2 %0, %1, %2;" : "=l"(r) : "l"(a), "l"(b)); return r;
}
__device__ __forceinline__ ull dup2(float v) {
    ull r; asm("mov.b64 %0, {%1, %1};" : "=l"(r) : "f"(v)); return r;
}
__device__ __forceinline__ float ex2f(float z) {
    float r; asm("ex2.approx.ftz.f32 %0, %1;" : "=f"(r) : "f"(z)); return r;
}
__device__ __forceinline__ float rcpf(float z) {
    float r; asm("rcp.approx.ftz.f32 %0, %1;" : "=f"(r) : "f"(z)); return r;
}
// tanh(a) where z = a*2*log2(e):  1 - 2/(2^z + 1).
__device__ __forceinline__ float tanh2(float z) {
    const float ex = ex2f(z);
    const float r  = rcpf(ex + 1.0f);
    return fmaf(-2.0f, r, 1.0f);
}

// ---------------------------------------------------------------------------
// Kernel A: q' = (x@Wt + bh)*C2 ; k' = (x@Wx)*C2.
// 8 rows/block, 512 threads, grid 512, 4-way split-K, 4-deep W ring.
// thread: g = tid&15 (4 u), rg = (tid>>4)&7 (row), part = tid>>7.
// ---------------------------------------------------------------------------
__global__ __launch_bounds__(512) void qk_kernel(
    const float4* __restrict__ x4,
    const ulonglong2* __restrict__ Wt2,
    const ulonglong2* __restrict__ Wx2,
    const float4* __restrict__ bh4,
    float4* __restrict__ gq4,
    float4* __restrict__ gk4) {
    __shared__ float xs[8 * 516];           // 16.5 KB
    __shared__ ulonglong2 red[3 * 128];     // 6 KB split-K partials

    const int tid  = threadIdx.x;
    const int row0 = blockIdx.x * 8;

    for (int i = tid; i < 8 * 128; i += 512) {
        const int r = i >> 7, c = i & 127;
        float4 v = x4[(size_t)(row0 + r) * 128 + c];
        float* dst = &xs[r * 516 + c * 4];
        dst[0] = v.x; dst[1] = v.y; dst[2] = v.z; dst[3] = v.w;
    }
    __syncthreads();

    const int g    = tid & 15;
    const int rg   = (tid >> 4) & 7;
    const int part = tid >> 7;              // 0..3

    const ulonglong2* Wb = (g < 8) ? (Wt2 + g) : (Wx2 + (g - 8));
    Wb += (size_t)part * 128 * 8;

    const float* x0 = &xs[rg * 516 + part * 128];

    ull a0 = 0, a1 = 0;

    ulonglong2 wbuf[4];
    #pragma unroll
    for (int p = 0; p < 4; p++) wbuf[p] = Wb[p * 8];

    #pragma unroll 4
    for (int d = 0; d < 128; d++) {
        ulonglong2 wv = wbuf[d & 3];
        if (d + 4 < 128) wbuf[d & 3] = Wb[(d + 4) * 8];
        ull xv = dup2(x0[d]);
        fma2(a0, xv, wv.x);
        fma2(a1, xv, wv.y);
    }

    if (part) red[(part - 1) * 128 + (tid & 127)] = make_ulonglong2(a0, a1);
    __syncthreads();

    if (part == 0) {
        #pragma unroll
        for (int p = 0; p < 3; p++) {
            ulonglong2 r0 = red[p * 128 + tid];
            a0 = add2(a0, r0.x);
            a1 = add2(a1, r0.y);
        }
        const float2 f0 = *reinterpret_cast<float2*>(&a0);
        const float2 f1 = *reinterpret_cast<float2*>(&a1);
        const int row = row0 + rg;
        if (g < 8) {
            float4 bb = bh4[g];
            gq4[(size_t)row * 8 + g] = make_float4(
                (f0.x + bb.x) * C2, (f0.y + bb.y) * C2,
                (f1.x + bb.z) * C2, (f1.y + bb.w) * C2);
        } else {
            gk4[(size_t)row * 8 + (g - 8)] = make_float4(
                f0.x * C2, f0.y * C2, f1.x * C2, f1.y * C2);
        }
    }
}

// ---------------------------------------------------------------------------
// Kernel B (R12-proven): banded attention, 2-barrier structure.
// ---------------------------------------------------------------------------
__global__ __launch_bounds__(256, 4) void attn_kernel(
    const float4* __restrict__ x4,
    const float4* __restrict__ gq4,
    const float4* __restrict__ gk4,
    const float*  __restrict__ Wa,
    const float*  __restrict__ ba,
    float4* __restrict__ out4) {
    __shared__ float  qs[TT * 36];
    __shared__ float  ks[JW * 36];
    __shared__ float2 e2s[JWP * TT];
    __shared__ float  wsum[8][8];
    __shared__ float4 was4[8];
    __shared__ float  baL_s;

    const int tid   = threadIdx.x;
    const int blk   = blockIdx.x;
    const int b     = blk >> 7;
    const int t0    = (blk & 127) * TT;
    const int jbase = t0 - WIDTH / 2;

    if (tid < 8) {
        float4 w = ((const float4*)Wa)[tid];
        was4[tid] = make_float4(w.x * LOG2E, w.y * LOG2E,
                                w.z * LOG2E, w.w * LOG2E);
    }
    if (tid == 0) baL_s = ba[0] * LOG2E;

    for (int i = tid; i < TT * 8; i += 256) {
        const int tt = i >> 3, w = i & 7;
        ((float4*)&qs[tt * 36])[w] = gq4[((size_t)(b * T + t0 + tt)) * 8 + w];
    }
    for (int i = tid; i < JW * 8; i += 256) {
        const int jj = i >> 3, w = i & 7;
        const int j = jbase + jj;
        ((float4*)&ks[jj * 36])[w] = (j >= 0 && j < T)
            ? gk4[((size_t)(b * T + j)) * 8 + w]
            : make_float4(0.f, 0.f, 0.f, 0.f);
    }
    __syncthreads();

    // ---- score phase ----
    {
        const int tt  = tid & 7;
        const int jj0 = tid >> 3;
        float4 qr[8];
        const float4* qp = (const float4*)&qs[tt * 36];
        #pragma unroll
        for (int gi = 0; gi < 8; gi++) qr[gi] = qp[gi];
        const float baL = baL_s;

        float ps = 0.0f;
        for (int jj = jj0; jj < JWP; jj += 32) {
            const int j = jbase + jj;
            float ev = 0.0f;
            if ((unsigned)j < (unsigned)T &&
                (unsigned)(jj - tt) < (unsigned)WIDTH) {
                const float4* kp = (const float4*)&ks[jj * 36];
                float s = baL;
                #pragma unroll
                for (int gi = 0; gi < 8; gi++) {
                    float4 k4 = kp[gi], w4 = was4[gi];
                    s = fmaf(tanh2(qr[gi].x + k4.x), w4.x, s);
                    s = fmaf(tanh2(qr[gi].y + k4.y), w4.y, s);
                    s = fmaf(tanh2(qr[gi].z + k4.z), w4.z, s);
                    s = fmaf(tanh2(qr[gi].w + k4.w), w4.w, s);
                }
                ev = ex2f(s);
            }
            e2s[jj * TT + tt] = make_float2(ev, ev);
            ps += ev;
        }
        ps += __shfl_xor_sync(0xffffffffu, ps, 8);
        ps += __shfl_xor_sync(0xffffffffu, ps, 16);
        const int w = tid >> 5, lane = tid & 31;
        if (lane < 8) wsum[w][lane] = ps;
    }
    __syncthreads();

    // ---- gather phase: MLP=4 ring ----
    const int dg  = tid & 127;
    const int h   = tid >> 7;
    const int ttb = h * 4;

    const int lo = max(ttb, -jbase);
    const int hi = min(ttb + 3 + (WIDTH - 1), (T - 1) - jbase);
    const int n  = hi - lo + 1;
    const int n4 = (n + 3) & ~3;

    ull acc[4][2];
    #pragma unroll
    for (int k = 0; k < 4; k++) { acc[k][0] = 0ULL; acc[k][1] = 0ULL; }

    const size_t xbase = (size_t)b * T;
    const float4* xp = x4 + (xbase + jbase + lo) * 128 + dg;
    const float2* ep = e2s + lo * TT + ttb;

    float4 buf[4];
    #pragma unroll
    for (int p = 0; p < 4; p++)
        buf[p] = (p < n) ? xp[(size_t)p * 128] : make_float4(0.f, 0.f, 0.f, 0.f);

    #pragma unroll 4
    for (int jj = 0; jj < n4; jj++) {
        float4 xv = buf[jj & 3];
        if (jj + 4 < n) buf[jj & 3] = xp[(size_t)(jj + 4) * 128];
        ulonglong2 xpk = *reinterpret_cast<ulonglong2*>(&xv);
        ulonglong2 e01 = *reinterpret_cast<const ulonglong2*>(ep + (size_t)jj * TT);
        ulonglong2 e23 = *reinterpret_cast<const ulonglong2*>(ep + (size_t)jj * TT + 2);
        fma2(acc[0][0], e01.x, xpk.x); fma2(acc[0][1], e01.x, xpk.y);
        fma2(acc[1][0], e01.y, xpk.x); fma2(acc[1][1], e01.y, xpk.y);
        fma2(acc[2][0], e23.x, xpk.x); fma2(acc[2][1], e23.x, xpk.y);
        fma2(acc[3][0], e23.y, xpk.x); fma2(acc[3][1], e23.y, xpk.y);
    }

    #pragma unroll
    for (int k = 0; k < 4; k++) {
        float s = 0.0f;
        #pragma unroll
        for (int w = 0; w < 8; w++) s += wsum[w][ttb + k];
        const float inv = __fdividef(1.0f, s + EPS);
        const float2 lo2 = *reinterpret_cast<float2*>(&acc[k][0]);
        const float2 hi2 = *reinterpret_cast<float2*>(&acc[k][1]);
        out4[(xbase + t0 + ttb + k) * 128 + dg] = make_float4(
            lo2.x * inv, lo2.y * inv, hi2.x * inv, hi2.y * inv);
    }
}

extern "C" void kernel_launch(void* const* d_in, const int* in_sizes, int n_in,
                              void* d_out, int out_size) {
    const float* x  = (const float*)d_in[0];
    const float* Wt = (const float*)d_in[1];
    const float* Wx = (const float*)d_in[2];
    const float* bh = (const float*)d_in[3];
    const float* Wa = (const float*)d_in[4];
    const float* ba = (const float*)d_in[5];
    float* out = (float*)d_out;

    float* gq;
    float* gk;
    cudaGetSymbolAddress((void**)&gq, g_q);
    cudaGetSymbolAddress((void**)&gk, g_k);

    qk_kernel<<<(B * T) / 8, 512>>>((const float4*)x,
                                    (const ulonglong2*)Wt,
                                    (const ulonglong2*)Wx,
                                    (const float4*)bh,
                                    (float4*)gq, (float4*)gk);
    attn_kernel<<<(B * T) / TT, 256>>>((const float4*)x,
                                       (const float4*)gq, (const float4*)gk,
                                       Wa, ba, (float4*)out);
}

// round 16
// speedup vs baseline: 1.2826x; 1.2826x over previous
#include <cuda_runtime.h>
#include <cuda_bf16.h>
#include <math.h>

#define B 4
#define T 1024
#define D 512
#define U 32
#define WIDTH 64
#define EPS 1e-7f
#define TT 8
#define JW 71
#define JWP 72

#define LOG2E 1.4426950408889634f
#define C2    2.8853900817779268f   // 2*log2(e)

// Scratch: q' = (x@Wt + bh)*C2, k' = (x@Wx)*C2, [B,T,U]
__device__ __align__(16) float g_q[B * T * U];
__device__ __align__(16) float g_k[B * T * U];

typedef unsigned long long ull;

__device__ __forceinline__ void fma2(ull& acc, ull a, ull b) {
    asm("fma.rn.f32x2 %0, %1, %2, %0;" : "+l"(acc) : "l"(a), "l"(b));
}
__device__ __forceinline__ ull add2(ull a, ull b) {
    ull r; asm("add.rn.f32x2 %0, %1, %2;" : "=l"(r) : "l"(a), "l"(b)); return r;
}
__device__ __forceinline__ ull dup2(float v) {
    ull r; asm("mov.b64 %0, {%1, %1};" : "=l"(r) : "f"(v)); return r;
}
__device__ __forceinline__ float ex2f(float z) {
    float r; asm("ex2.approx.ftz.f32 %0, %1;" : "=f"(r) : "f"(z)); return r;
}
__device__ __forceinline__ float rcpf(float z) {
    float r; asm("rcp.approx.ftz.f32 %0, %1;" : "=f"(r) : "f"(z)); return r;
}
// tanh(a) where z = a*2*log2(e):  1 - 2/(2^z + 1).
__device__ __forceinline__ float tanh2(float z) {
    const float ex = ex2f(z);
    const float r  = rcpf(ex + 1.0f);
    return fmaf(-2.0f, r, 1.0f);
}

// ---------------------------------------------------------------------------
// Kernel A (R12 exact): q' = (x@Wt + bh)*C2 ; k' = (x@Wx)*C2.
// 16 rows/block, 512 threads, grid 256, 4-way split-K, 4-deep W ring.
// ---------------------------------------------------------------------------
__global__ __launch_bounds__(512) void qk_kernel(
    const float4* __restrict__ x4,
    const ulonglong2* __restrict__ Wt2,
    const ulonglong2* __restrict__ Wx2,
    const float4* __restrict__ bh4,
    float4* __restrict__ gq4,
    float4* __restrict__ gk4) {
    __shared__ float xs[16 * 516];
    __shared__ ulonglong2 red[3 * 128][2];

    const int tid  = threadIdx.x;
    const int row0 = blockIdx.x * 16;

    for (int i = tid; i < 16 * 128; i += 512) {
        const int r = i >> 7, c = i & 127;
        float4 v = x4[(size_t)(row0 + r) * 128 + c];
        float* dst = &xs[r * 516 + c * 4];
        dst[0] = v.x; dst[1] = v.y; dst[2] = v.z; dst[3] = v.w;
    }
    __syncthreads();

    const int g    = tid & 15;
    const int rg   = (tid >> 4) & 15;
    const int part = tid >> 7;

    const ulonglong2* Wb = (g < 8) ? (Wt2 + g) : (Wx2 + (g - 8));
    Wb += (size_t)part * 128 * 8;

    const float* x0 = &xs[(2 * (rg & 7)) * 516 + part * 128];
    const float* x1 = x0 + 516;

    ull a00 = 0, a01 = 0, a10 = 0, a11 = 0;

    ulonglong2 wbuf[4];
    #pragma unroll
    for (int p = 0; p < 4; p++) wbuf[p] = Wb[p * 8];

    #pragma unroll 4
    for (int d = 0; d < 128; d++) {
        ulonglong2 wv = wbuf[d & 3];
        if (d + 4 < 128) wbuf[d & 3] = Wb[(d + 4) * 8];
        ull xv0 = dup2(x0[d]);
        ull xv1 = dup2(x1[d]);
        fma2(a00, xv0, wv.x); fma2(a01, xv0, wv.y);
        fma2(a10, xv1, wv.x); fma2(a11, xv1, wv.y);
    }

    if (part) {
        red[(part - 1) * 128 + (tid & 127)][0] = make_ulonglong2(a00, a01);
        red[(part - 1) * 128 + (tid & 127)][1] = make_ulonglong2(a10, a11);
    }
    __syncthreads();

    if (part == 0) {
        #pragma unroll
        for (int p = 0; p < 3; p++) {
            ulonglong2 r0 = red[p * 128 + tid][0];
            ulonglong2 r1 = red[p * 128 + tid][1];
            a00 = add2(a00, r0.x); a01 = add2(a01, r0.y);
            a10 = add2(a10, r1.x); a11 = add2(a11, r1.y);
        }
        const float2 f00 = *reinterpret_cast<float2*>(&a00);
        const float2 f01 = *reinterpret_cast<float2*>(&a01);
        const float2 f10 = *reinterpret_cast<float2*>(&a10);
        const float2 f11 = *reinterpret_cast<float2*>(&a11);
        const int row = row0 + 2 * (rg & 7);
        if (g < 8) {
            float4 bb = bh4[g];
            gq4[(size_t)row * 8 + g] = make_float4(
                (f00.x + bb.x) * C2, (f00.y + bb.y) * C2,
                (f01.x + bb.z) * C2, (f01.y + bb.w) * C2);
            gq4[(size_t)(row + 1) * 8 + g] = make_float4(
                (f10.x + bb.x) * C2, (f10.y + bb.y) * C2,
                (f11.x + bb.z) * C2, (f11.y + bb.w) * C2);
        } else {
            gk4[(size_t)row * 8 + (g - 8)] = make_float4(
                f00.x * C2, f00.y * C2, f01.x * C2, f01.y * C2);
            gk4[(size_t)(row + 1) * 8 + (g - 8)] = make_float4(
                f10.x * C2, f10.y * C2, f11.x * C2, f11.y * C2);
        }
    }
}

// ---------------------------------------------------------------------------
// Kernel B (R12 + 5 blocks/SM): banded attention, 2-barrier structure.
// ---------------------------------------------------------------------------
__global__ __launch_bounds__(256, 5) void attn_kernel(
    const float4* __restrict__ x4,
    const float4* __restrict__ gq4,
    const float4* __restrict__ gk4,
    const float*  __restrict__ Wa,
    const float*  __restrict__ ba,
    float4* __restrict__ out4) {
    __shared__ float  qs[TT * 36];
    __shared__ float  ks[JW * 36];
    __shared__ float2 e2s[JWP * TT];
    __shared__ float  wsum[8][8];
    __shared__ float4 was4[8];
    __shared__ float  baL_s;

    const int tid   = threadIdx.x;
    const int blk   = blockIdx.x;
    const int b     = blk >> 7;
    const int t0    = (blk & 127) * TT;
    const int jbase = t0 - WIDTH / 2;

    if (tid < 8) {
        float4 w = ((const float4*)Wa)[tid];
        was4[tid] = make_float4(w.x * LOG2E, w.y * LOG2E,
                                w.z * LOG2E, w.w * LOG2E);
    }
    if (tid == 0) baL_s = ba[0] * LOG2E;

    for (int i = tid; i < TT * 8; i += 256) {
        const int tt = i >> 3, w = i & 7;
        ((float4*)&qs[tt * 36])[w] = gq4[((size_t)(b * T + t0 + tt)) * 8 + w];
    }
    for (int i = tid; i < JW * 8; i += 256) {
        const int jj = i >> 3, w = i & 7;
        const int j = jbase + jj;
        ((float4*)&ks[jj * 36])[w] = (j >= 0 && j < T)
            ? gk4[((size_t)(b * T + j)) * 8 + w]
            : make_float4(0.f, 0.f, 0.f, 0.f);
    }
    __syncthreads();

    // ---- score phase ----
    {
        const int tt  = tid & 7;
        const int jj0 = tid >> 3;
        const float4* qp = (const float4*)&qs[tt * 36];
        const float baL = baL_s;

        float ps = 0.0f;
        for (int jj = jj0; jj < JWP; jj += 32) {
            const int j = jbase + jj;
            float ev = 0.0f;
            if ((unsigned)j < (unsigned)T &&
                (unsigned)(jj - tt) < (unsigned)WIDTH) {
                const float4* kp = (const float4*)&ks[jj * 36];
                float s = baL;
                #pragma unroll
                for (int gi = 0; gi < 8; gi++) {
                    float4 q4 = qp[gi], k4 = kp[gi], w4 = was4[gi];
                    s = fmaf(tanh2(q4.x + k4.x), w4.x, s);
                    s = fmaf(tanh2(q4.y + k4.y), w4.y, s);
                    s = fmaf(tanh2(q4.z + k4.z), w4.z, s);
                    s = fmaf(tanh2(q4.w + k4.w), w4.w, s);
                }
                ev = ex2f(s);
            }
            e2s[jj * TT + tt] = make_float2(ev, ev);
            ps += ev;
        }
        ps += __shfl_xor_sync(0xffffffffu, ps, 8);
        ps += __shfl_xor_sync(0xffffffffu, ps, 16);
        const int w = tid >> 5, lane = tid & 31;
        if (lane < 8) wsum[w][lane] = ps;
    }
    __syncthreads();

    // ---- gather phase: MLP=4 ring ----
    const int dg  = tid & 127;
    const int h   = tid >> 7;
    const int ttb = h * 4;

    const int lo = max(ttb, -jbase);
    const int hi = min(ttb + 3 + (WIDTH - 1), (T - 1) - jbase);
    const int n  = hi - lo + 1;
    const int n4 = (n + 3) & ~3;

    ull acc[4][2];
    #pragma unroll
    for (int k = 0; k < 4; k++) { acc[k][0] = 0ULL; acc[k][1] = 0ULL; }

    const size_t xbase = (size_t)b * T;
    const float4* xp = x4 + (xbase + jbase + lo) * 128 + dg;
    const float2* ep = e2s + lo * TT + ttb;

    float4 buf[4];
    #pragma unroll
    for (int p = 0; p < 4; p++)
        buf[p] = (p < n) ? xp[(size_t)p * 128] : make_float4(0.f, 0.f, 0.f, 0.f);

    #pragma unroll 4
    for (int jj = 0; jj < n4; jj++) {
        float4 xv = buf[jj & 3];
        if (jj + 4 < n) buf[jj & 3] = xp[(size_t)(jj + 4) * 128];
        ulonglong2 xpk = *reinterpret_cast<ulonglong2*>(&xv);
        ulonglong2 e01 = *reinterpret_cast<const ulonglong2*>(ep + (size_t)jj * TT);
        ulonglong2 e23 = *reinterpret_cast<const ulonglong2*>(ep + (size_t)jj * TT + 2);
        fma2(acc[0][0], e01.x, xpk.x); fma2(acc[0][1], e01.x, xpk.y);
        fma2(acc[1][0], e01.y, xpk.x); fma2(acc[1][1], e01.y, xpk.y);
        fma2(acc[2][0], e23.x, xpk.x); fma2(acc[2][1], e23.x, xpk.y);
        fma2(acc[3][0], e23.y, xpk.x); fma2(acc[3][1], e23.y, xpk.y);
    }

    #pragma unroll
    for (int k = 0; k < 4; k++) {
        float s = 0.0f;
        #pragma unroll
        for (int w = 0; w < 8; w++) s += wsum[w][ttb + k];
        const float inv = __fdividef(1.0f, s + EPS);
        const float2 lo2 = *reinterpret_cast<float2*>(&acc[k][0]);
        const float2 hi2 = *reinterpret_cast<float2*>(&acc[k][1]);
        out4[(xbase + t0 + ttb + k) * 128 + dg] = make_float4(
            lo2.x * inv, lo2.y * inv, hi2.x * inv, hi2.y * inv);
    }
}

extern "C" void kernel_launch(void* const* d_in, const int* in_sizes, int n_in,
                              void* d_out, int out_size) {
    const float* x  = (const float*)d_in[0];
    const float* Wt = (const float*)d_in[1];
    const float* Wx = (const float*)d_in[2];
    const float* bh = (const float*)d_in[3];
    const float* Wa = (const float*)d_in[4];
    const float* ba = (const float*)d_in[5];
    float* out = (float*)d_out;

    float* gq;
    float* gk;
    cudaGetSymbolAddress((void**)&gq, g_q);
    cudaGetSymbolAddress((void**)&gk, g_k);

    qk_kernel<<<(B * T) / 16, 512>>>((const float4*)x,
                                     (const ulonglong2*)Wt,
                                     (const ulonglong2*)Wx,
                                     (const float4*)bh,
                                     (float4*)gq, (float4*)gk);
    attn_kernel<<<(B * T) / TT, 256>>>((const float4*)x,
                                       (const float4*)gq, (const float4*)gk,
                                       Wa, ba, (float4*)out);
}